// round 2
// baseline (speedup 1.0000x reference)
#include <cuda_runtime.h>

#define B 512
#define T 2048
#define K 32
#define FULL 0xffffffffu

// m-trace: m[b][t][j] = max_i (s_i(t-1) + trans[i][j])  (slots t=1..T-1 used)
__device__ float g_m[(size_t)B * T * K];

#define ADD2(out, a, b) asm("add.rn.f32x2 %0, %1, %2;" : "=l"(out) : "l"(a), "l"(b))

__global__ void __launch_bounds__(32, 4) crf_viterbi_kernel(
    const float* __restrict__ pot,     // [B, T, K]
    const float* __restrict__ trans,   // [K, K]
    float* __restrict__ out)           // [B, T, K] one-hot
{
    __shared__ float trCol[K * K];                  // trCol[j*K+i] = trans[i][j]
    __shared__ __align__(16) float st[2][K];
    __shared__ unsigned char tagSm[T];

    const int lane = threadIdx.x;
    const int b    = blockIdx.x;
    const float* p = pot + (size_t)b * T * K + lane;
    float* mb      = g_m + (size_t)b * T * K + lane;

    // packed transition column `lane`: tj2[q] = (trans[2q][lane], trans[2q+1][lane])
    unsigned long long tj2[16];
#pragma unroll
    for (int q = 0; q < 16; q++) {
        float lo = __ldg(trans + (2 * q) * K + lane);
        float hi = __ldg(trans + (2 * q + 1) * K + lane);
        asm("mov.b64 %0, {%1, %2};" : "=l"(tj2[q]) : "f"(lo), "f"(hi));
    }
    // transposed transitions for backtrack
#pragma unroll
    for (int i = 0; i < K; i++) trCol[lane * K + i] = trans[i * K + lane];

    float s = p[0];
    const float pot0 = s;

    // 8-deep potential prefetch (~8 steps * ~90cyc >= DRAM latency)
    float pf[8];
#pragma unroll
    for (int k = 0; k < 8; k++) pf[k] = p[(size_t)(1 + k) * K];

    float mlast = 0.0f;

    // ---------------- forward: values only ----------------
    for (int w = 0; w < 256; w++) {
#pragma unroll
        for (int k = 0; k < 8; k++) {
            const int t = 1 + 8 * w + k;
            if (t < T) {
                const int buf = k & 1;
                st[buf][lane] = s;
                __syncwarp();
                const ulonglong2* sp = (const ulonglong2*)st[buf];

                unsigned long long v2[16];
#pragma unroll
                for (int q = 0; q < 8; q++) {
                    ulonglong2 r = sp[q];
                    ADD2(v2[2 * q],     r.x, tj2[2 * q]);
                    ADD2(v2[2 * q + 1], r.y, tj2[2 * q + 1]);
                }
                float m0[16];
#pragma unroll
                for (int q = 0; q < 16; q++) {
                    float lo, hi;
                    asm("mov.b64 {%0, %1}, %2;" : "=f"(lo), "=f"(hi) : "l"(v2[q]));
                    m0[q] = fmaxf(lo, hi);
                }
                float m1[8];
#pragma unroll
                for (int q = 0; q < 8; q++) m1[q] = fmaxf(m0[2 * q], m0[2 * q + 1]);
                float m2[4];
#pragma unroll
                for (int q = 0; q < 4; q++) m2[q] = fmaxf(m1[2 * q], m1[2 * q + 1]);
                float m3a = fmaxf(m2[0], m2[1]);
                float m3b = fmaxf(m2[2], m2[3]);
                float m   = fmaxf(m3a, m3b);

                mb[(size_t)t * K] = m;          // trace (off critical path)

                const float pcur = pf[k];
                int tn = t + 8; if (tn > T - 1) tn = T - 1;
                pf[k] = p[(size_t)tn * K];

                s = m + pcur;
                mlast = m;
            }
        }
    }

    // ---------------- final tag: first-index argmax over lanes ----------------
    float mm = s;
#pragma unroll
    for (int off = 16; off; off >>= 1) mm = fmaxf(mm, __shfl_xor_sync(FULL, mm, off));
    unsigned fmsk = __ballot_sync(FULL, s == mm);
    int tag = __ffs(fmsk) - 1;
    if (lane == 0) tagSm[T - 1] = (unsigned char)tag;

    // ---------------- backtrack: recompute argmax via ballot ----------------
    float mcur = mlast;                         // m(T-1) vector across lanes

    // ring prefetch for t' = T-2 .. 1 : m(t') and pot(t')
    float mr[8], pr[8];
#pragma unroll
    for (int d = 0; d < 8; d++) {
        const int tp = T - 2 - d;
        mr[d] = mb[(size_t)tp * K];
        pr[d] = p[(size_t)tp * K];
    }

    // main loop: t from T-1 down to 2  (computes tag(t-1)), 2046 iterations
    for (int nb = 0; nb < 256; nb++) {
#pragma unroll
        for (int d = 0; d < 8; d++) {
            const int n = nb * 8 + d;
            if (n < T - 2) {
                const int tp = T - 2 - n;               // t' = t-1
                const float target = __shfl_sync(FULL, mcur, tag);
                const float tv = trCol[tag * K + lane];
                const float sprev = mr[d] + pr[d];      // s(t')
                const float v = sprev + tv;
                unsigned msk = __ballot_sync(FULL, v == target);
                const float mnext = mr[d];
                // refill ring (addresses tag-independent)
                const int tp2 = tp - 8;
                if (tp2 >= 1) {
                    mr[d] = mb[(size_t)tp2 * K];
                    pr[d] = p[(size_t)tp2 * K];
                }
                tag = __ffs(msk) - 1;
                if (lane == 0) tagSm[tp] = (unsigned char)tag;
                mcur = mnext;
            }
        }
    }
    // last step: t=1 -> tag(0), s(0) = pot(0)
    {
        const float target = __shfl_sync(FULL, mcur, tag);
        const float tv = trCol[tag * K + lane];
        const float v = pot0 + tv;
        unsigned msk = __ballot_sync(FULL, v == target);
        tag = __ffs(msk) - 1;
        if (lane == 0) tagSm[0] = (unsigned char)tag;
    }
    __syncwarp();

    // ---------------- one-hot output, 128-bit stores ----------------
    float* ob = out + (size_t)b * T * K;
    const int q  = lane & 7;
    const int dt = lane >> 3;
    for (int t0 = 0; t0 < T; t0 += 4) {
        const int t  = t0 + dt;
        const int tg = (int)tagSm[t];
        float4 val;
        val.x = (tg == 4 * q + 0) ? 1.0f : 0.0f;
        val.y = (tg == 4 * q + 1) ? 1.0f : 0.0f;
        val.z = (tg == 4 * q + 2) ? 1.0f : 0.0f;
        val.w = (tg == 4 * q + 3) ? 1.0f : 0.0f;
        *(float4*)(ob + (size_t)t * K + 4 * q) = val;
    }
}

extern "C" void kernel_launch(void* const* d_in, const int* in_sizes, int n_in,
                              void* d_out, int out_size)
{
    const float* pot   = (const float*)d_in[0];
    const float* trans = (const float*)d_in[1];
    float* outp        = (float*)d_out;
    crf_viterbi_kernel<<<B, K>>>(pot, trans, outp);
}

// round 3
// speedup vs baseline: 3.7336x; 3.7336x over previous
#include <cuda_runtime.h>
#include <cstdint>

#define B 512
#define T 2048
#define K 32
#define CH 32            // time steps per staged chunk
#define NCH (T / CH)     // 64 chunks
#define FULL 0xffffffffu

// m-trace: m[b][t][j] = max_i (s_i(t-1) + trans[i][j])  (slots t=1..T-1 used)
__device__ float g_m[(size_t)B * T * K];

#define ADD2(out, a, b) asm("add.rn.f32x2 %0, %1, %2;" : "=l"(out) : "l"(a), "l"(b))
#define UNPK(lo, hi, v) asm("mov.b64 {%0, %1}, %2;" : "=f"(lo), "=f"(hi) : "l"(v))

__device__ __forceinline__ void cp16(uint32_t saddr, const void* gptr) {
    asm volatile("cp.async.cg.shared.global [%0], [%1], 16;" :: "r"(saddr), "l"(gptr));
}
#define CP_COMMIT()  asm volatile("cp.async.commit_group;")
#define CP_WAIT(n)   asm volatile("cp.async.wait_group %0;" :: "n"(n))

__global__ void __launch_bounds__(32, 4) crf_viterbi_kernel(
    const float* __restrict__ pot,     // [B, T, K]
    const float* __restrict__ trans,   // [K, K]
    float* __restrict__ out)           // [B, T, K] one-hot
{
    __shared__ __align__(16) float potS[2][CH * K];   // 8 KB
    __shared__ __align__(16) float mS[2][CH * K];     // 8 KB
    __shared__ float trColS[K * K];                   // 4 KB : trColS[j*K+i] = trans[i][j]
    __shared__ __align__(16) float stS[2][K];
    __shared__ unsigned char tagS[T];

    const int lane = threadIdx.x;
    const int b    = blockIdx.x;
    const char* pB = (const char*)(pot + (size_t)b * T * K);
    const char* mB = (const char*)(g_m + (size_t)b * T * K);
    float* mOut    = g_m + (size_t)b * T * K + lane;

    const uint32_t potA0 = (uint32_t)__cvta_generic_to_shared(potS[0]);
    const uint32_t potA1 = (uint32_t)__cvta_generic_to_shared(potS[1]);
    const uint32_t mA0   = (uint32_t)__cvta_generic_to_shared(mS[0]);
    const uint32_t mA1   = (uint32_t)__cvta_generic_to_shared(mS[1]);

    // packed transition column `lane`: tj2[q] = (trans[2q][lane], trans[2q+1][lane])
    unsigned long long tj2[16];
#pragma unroll
    for (int q = 0; q < 16; q++) {
        float lo = __ldg(trans + (2 * q) * K + lane);
        float hi = __ldg(trans + (2 * q + 1) * K + lane);
        asm("mov.b64 %0, {%1, %2};" : "=l"(tj2[q]) : "f"(lo), "f"(hi));
    }
    // transposed transitions for backtrack
#pragma unroll
    for (int i = 0; i < K; i++) trColS[lane * K + i] = trans[i * K + lane];

    // ---- stage forward chunks 0 and 1 ----
    {
#pragma unroll
        for (int i = 0; i < 8; i++)
            cp16(potA0 + lane * 16 + i * 512, pB + lane * 16 + i * 512);
        CP_COMMIT();
#pragma unroll
        for (int i = 0; i < 8; i++)
            cp16(potA1 + lane * 16 + i * 512, pB + 4096 + lane * 16 + i * 512);
        CP_COMMIT();
    }
    CP_WAIT(1);
    __syncwarp();

    float s = potS[0][lane];           // s(0) = pot(0)
    const float pot0 = s;
    float mlast = 0.0f;

    // ================= forward (values only) =================
    for (int c = 0; c < NCH; c++) {
        const float* pc = potS[c & 1];
        for (int rb = 0; rb < CH / 8; rb++) {
#pragma unroll
            for (int k = 0; k < 8; k++) {
                const int r = rb * 8 + k;
                const int t = c * CH + r;
                if (t >= 1) {
                    const float pcur = pc[r * K + lane];      // LDS, off-chain
                    const int bb = t & 1;
                    stS[bb][lane] = s;
                    __syncwarp();
                    const ulonglong2* sp = (const ulonglong2*)(stS[bb]);

                    unsigned long long v2[16];
#pragma unroll
                    for (int q = 0; q < 8; q++) {
                        ulonglong2 rr = sp[q];
                        ADD2(v2[2 * q],     rr.x, tj2[2 * q]);
                        ADD2(v2[2 * q + 1], rr.y, tj2[2 * q + 1]);
                    }
                    float m0[16];
#pragma unroll
                    for (int q = 0; q < 16; q++) {
                        float lo, hi; UNPK(lo, hi, v2[q]);
                        m0[q] = fmaxf(lo, hi);
                    }
                    float m1[8];
#pragma unroll
                    for (int q = 0; q < 8; q++) m1[q] = fmaxf(m0[2 * q], m0[2 * q + 1]);
                    float m2[4];
#pragma unroll
                    for (int q = 0; q < 4; q++) m2[q] = fmaxf(m1[2 * q], m1[2 * q + 1]);
                    const float m = fmaxf(fmaxf(m2[0], m2[1]), fmaxf(m2[2], m2[3]));

                    mOut[(size_t)t * K] = m;                  // trace store, off-chain
                    s = m + pcur;
                    mlast = m;
                }
            }
        }
        // stage chunk c+2 into the buffer we just finished, then ensure c+1 ready
        if (c + 2 < NCH) {
            const uint32_t dst = ((c & 1) == 0) ? potA0 : potA1;
            const char* src = pB + (size_t)(c + 2) * 4096;
#pragma unroll
            for (int i = 0; i < 8; i++)
                cp16(dst + lane * 16 + i * 512, src + lane * 16 + i * 512);
            CP_COMMIT();
            CP_WAIT(1);
            __syncwarp();
        } else if (c + 1 < NCH) {
            CP_WAIT(0);
            __syncwarp();
        }
    }

    // ---- final tag: first-index argmax over lanes of s(T-1) ----
    float mm = s;
#pragma unroll
    for (int off = 16; off; off >>= 1) mm = fmaxf(mm, __shfl_xor_sync(FULL, mm, off));
    int tag = __ffs(__ballot_sync(FULL, s == mm)) - 1;
    if (lane == 0) tagS[T - 1] = (unsigned char)tag;

    // ---- stage backtrack chunks 63 and 62 (m + pot rows) ----
    {
        const uint32_t mD[2]   = { mA0, mA1 };
        const uint32_t pD[2]   = { potA0, potA1 };
#pragma unroll
        for (int cc = 0; cc < 2; cc++) {
            const int c = NCH - 1 - cc;           // 63, 62
            const char* gm = mB + (size_t)c * 4096;
            const char* gp = pB + (size_t)c * 4096;
            const uint32_t md = mD[c & 1], pd = pD[c & 1];
#pragma unroll
            for (int i = 0; i < 8; i++) cp16(md + lane * 16 + i * 512, gm + lane * 16 + i * 512);
#pragma unroll
            for (int i = 0; i < 8; i++) cp16(pd + lane * 16 + i * 512, gp + lane * 16 + i * 512);
            CP_COMMIT();
        }
    }
    CP_WAIT(1);
    __syncwarp();

    // ================= backtrack: recompute argmax via ballot =================
    float mcur = mlast;                            // m(T-1) across lanes
    for (int c = NCH - 1; c >= 0; c--) {
        const float* mc  = mS[c & 1];
        const float* pcS = potS[c & 1];
        const int rhi = (c == NCH - 1) ? CH - 2 : CH - 1;   // first consumed tp = T-2
        const int rlo = (c == 0) ? 1 : 0;
#pragma unroll 4
        for (int r = rhi; r >= rlo; r--) {
            const int tp = c * CH + r;                       // tp = t-1
            const float target = __shfl_sync(FULL, mcur, tag);
            const float tv = trColS[tag * K + lane];
            const float mprev = mc[r * K + lane];
            const float pprev = pcS[r * K + lane];
            const float v = (mprev + pprev) + tv;
            const unsigned msk = __ballot_sync(FULL, v == target);
            tag = __ffs(msk) - 1;
            if (lane == 0) tagS[tp] = (unsigned char)tag;
            mcur = mprev;
        }
        if (c - 2 >= 0) {
            const uint32_t md = ((c & 1) == 0) ? mA0 : mA1;  // (c-2) same parity
            const uint32_t pd = ((c & 1) == 0) ? potA0 : potA1;
            const char* gm = mB + (size_t)(c - 2) * 4096;
            const char* gp = pB + (size_t)(c - 2) * 4096;
#pragma unroll
            for (int i = 0; i < 8; i++) cp16(md + lane * 16 + i * 512, gm + lane * 16 + i * 512);
#pragma unroll
            for (int i = 0; i < 8; i++) cp16(pd + lane * 16 + i * 512, gp + lane * 16 + i * 512);
            CP_COMMIT();
            CP_WAIT(1);
            __syncwarp();
        } else if (c - 1 >= 0) {
            CP_WAIT(0);
            __syncwarp();
        }
    }
    // last step: t=1 -> tag(0), s(0) = pot(0)
    {
        const float target = __shfl_sync(FULL, mcur, tag);
        const float tv = trColS[tag * K + lane];
        const float v = pot0 + tv;
        tag = __ffs(__ballot_sync(FULL, v == target)) - 1;
        if (lane == 0) tagS[0] = (unsigned char)tag;
    }
    __syncwarp();

    // ================= one-hot output, 128-bit stores =================
    float* ob = out + (size_t)b * T * K;
    const int q  = lane & 7;
    const int dt = lane >> 3;
    for (int t0 = 0; t0 < T; t0 += 4) {
        const int t  = t0 + dt;
        const int tg = (int)tagS[t];
        float4 val;
        val.x = (tg == 4 * q + 0) ? 1.0f : 0.0f;
        val.y = (tg == 4 * q + 1) ? 1.0f : 0.0f;
        val.z = (tg == 4 * q + 2) ? 1.0f : 0.0f;
        val.w = (tg == 4 * q + 3) ? 1.0f : 0.0f;
        *(float4*)(ob + (size_t)t * K + 4 * q) = val;
    }
}

extern "C" void kernel_launch(void* const* d_in, const int* in_sizes, int n_in,
                              void* d_out, int out_size)
{
    const float* pot   = (const float*)d_in[0];
    const float* trans = (const float*)d_in[1];
    float* outp        = (float*)d_out;
    crf_viterbi_kernel<<<B, K>>>(pot, trans, outp);
}

// round 4
// speedup vs baseline: 3.7795x; 1.0123x over previous
#include <cuda_runtime.h>
#include <cstdint>

#define B 512
#define T 2048
#define K 32
#define CH 32            // time steps per staged chunk
#define NCH (T / CH)     // 64 chunks
#define FULL 0xffffffffu

// m-trace: m[b][t][j] = max_i (s_i(t-1) + trans[i][j])  (slots t=1..T-1 used)
__device__ float g_m[(size_t)B * T * K];

#define ADD2(out, a, b) asm("add.rn.f32x2 %0, %1, %2;" : "=l"(out) : "l"(a), "l"(b))
#define UNPK(lo, hi, v) asm("mov.b64 {%0, %1}, %2;" : "=f"(lo), "=f"(hi) : "l"(v))
#define BARW()          asm volatile("bar.sync 0;" ::: "memory")

__device__ __forceinline__ void cp16(uint32_t saddr, const void* gptr) {
    asm volatile("cp.async.cg.shared.global [%0], [%1], 16;" :: "r"(saddr), "l"(gptr));
}
#define CP_COMMIT()  asm volatile("cp.async.commit_group;")
#define CP_WAIT(n)   asm volatile("cp.async.wait_group %0;" :: "n"(n))

__global__ void __launch_bounds__(32, 4) crf_viterbi_kernel(
    const float* __restrict__ pot,     // [B, T, K]
    const float* __restrict__ trans,   // [K, K]
    float* __restrict__ out)           // [B, T, K] one-hot
{
    __shared__ __align__(16) float potS[2][CH * K];   // 8 KB
    __shared__ __align__(16) float mS[2][CH * K];     // 8 KB
    __shared__ float trColS[K * K];                   // 4 KB : trColS[j*K+i] = trans[i][j]
    __shared__ __align__(16) float stS[2][K];

    const int lane = threadIdx.x;
    const int b    = blockIdx.x;
    const char* pB = (const char*)(pot + (size_t)b * T * K);
    const char* mB = (const char*)(g_m + (size_t)b * T * K);
    float* mOut    = g_m + (size_t)b * T * K + lane;
    float* ob      = out + (size_t)b * T * K + lane;

    const uint32_t potA0 = (uint32_t)__cvta_generic_to_shared(potS[0]);
    const uint32_t potA1 = (uint32_t)__cvta_generic_to_shared(potS[1]);
    const uint32_t mA0   = (uint32_t)__cvta_generic_to_shared(mS[0]);
    const uint32_t mA1   = (uint32_t)__cvta_generic_to_shared(mS[1]);

    // packed transition column `lane`: tj2[q] = (trans[2q][lane], trans[2q+1][lane])
    unsigned long long tj2[16];
#pragma unroll
    for (int q = 0; q < 16; q++) {
        float lo = __ldg(trans + (2 * q) * K + lane);
        float hi = __ldg(trans + (2 * q + 1) * K + lane);
        asm("mov.b64 %0, {%1, %2};" : "=l"(tj2[q]) : "f"(lo), "f"(hi));
    }
    // transposed transitions for backtrack
#pragma unroll
    for (int i = 0; i < K; i++) trColS[lane * K + i] = trans[i * K + lane];

    // ---- stage forward chunks 0 and 1 ----
    {
#pragma unroll
        for (int i = 0; i < 8; i++)
            cp16(potA0 + lane * 16 + i * 512, pB + lane * 16 + i * 512);
        CP_COMMIT();
#pragma unroll
        for (int i = 0; i < 8; i++)
            cp16(potA1 + lane * 16 + i * 512, pB + 4096 + lane * 16 + i * 512);
        CP_COMMIT();
    }
    CP_WAIT(1);
    BARW();

    float s = potS[0][lane];           // s(0) = pot(0)
    const float pot0 = s;
    float mlast = 0.0f;

    // ================= forward (values only) =================
    for (int c = 0; c < NCH; c++) {
        const float* pc = potS[c & 1];
        for (int rb = 0; rb < CH / 8; rb++) {
#pragma unroll
            for (int k = 0; k < 8; k++) {
                const int r = rb * 8 + k;
                const int t = c * CH + r;
                if (t >= 1) {
                    const float pcur = pc[r * K + lane];      // LDS, off-chain
                    const int bb = t & 1;
                    stS[bb][lane] = s;
                    BARW();
                    const ulonglong2* sp = (const ulonglong2*)(stS[bb]);

                    unsigned long long v2[16];
#pragma unroll
                    for (int q = 0; q < 8; q++) {
                        ulonglong2 rr = sp[q];
                        ADD2(v2[2 * q],     rr.x, tj2[2 * q]);
                        ADD2(v2[2 * q + 1], rr.y, tj2[2 * q + 1]);
                    }
                    float m0[16];
#pragma unroll
                    for (int q = 0; q < 16; q++) {
                        float lo, hi; UNPK(lo, hi, v2[q]);
                        m0[q] = fmaxf(lo, hi);
                    }
                    float m1[8];
#pragma unroll
                    for (int q = 0; q < 8; q++) m1[q] = fmaxf(m0[2 * q], m0[2 * q + 1]);
                    float m2[4];
#pragma unroll
                    for (int q = 0; q < 4; q++) m2[q] = fmaxf(m1[2 * q], m1[2 * q + 1]);
                    const float m = fmaxf(fmaxf(m2[0], m2[1]), fmaxf(m2[2], m2[3]));

                    mOut[(size_t)t * K] = m;                  // trace store, off-chain
                    s = m + pcur;
                    mlast = m;
                }
            }
        }
        // stage chunk c+2 into the buffer we just finished, then ensure c+1 ready
        if (c + 2 < NCH) {
            const uint32_t dst = ((c & 1) == 0) ? potA0 : potA1;
            const char* src = pB + (size_t)(c + 2) * 4096;
#pragma unroll
            for (int i = 0; i < 8; i++)
                cp16(dst + lane * 16 + i * 512, src + lane * 16 + i * 512);
            CP_COMMIT();
            CP_WAIT(1);
            BARW();
        } else if (c + 1 < NCH) {
            CP_WAIT(0);
            BARW();
        }
    }

    // ---- final tag: first-index argmax over lanes of s(T-1) ----
    float mm = s;
#pragma unroll
    for (int off = 16; off; off >>= 1) mm = fmaxf(mm, __shfl_xor_sync(FULL, mm, off));
    int tag = __ffs(__ballot_sync(FULL, s == mm)) - 1;
    ob[(size_t)(T - 1) * K] = (lane == tag) ? 1.0f : 0.0f;    // one-hot row T-1

    // ---- stage backtrack chunks 63 and 62 (m + pot rows) ----
    {
        const uint32_t mD[2] = { mA0, mA1 };
        const uint32_t pD[2] = { potA0, potA1 };
#pragma unroll
        for (int cc = 0; cc < 2; cc++) {
            const int c = NCH - 1 - cc;           // 63, 62
            const char* gm = mB + (size_t)c * 4096;
            const char* gp = pB + (size_t)c * 4096;
            const uint32_t md = mD[c & 1], pd = pD[c & 1];
#pragma unroll
            for (int i = 0; i < 8; i++) cp16(md + lane * 16 + i * 512, gm + lane * 16 + i * 512);
#pragma unroll
            for (int i = 0; i < 8; i++) cp16(pd + lane * 16 + i * 512, gp + lane * 16 + i * 512);
            CP_COMMIT();
        }
    }
    CP_WAIT(1);
    BARW();

    // ================= backtrack: recompute argmax via ballot, fused one-hot ==========
    float mcur = mlast;                            // m(T-1) across lanes
    for (int c = NCH - 1; c >= 0; c--) {
        const float* mc  = mS[c & 1];
        const float* pcS = potS[c & 1];
        const int rhi = (c == NCH - 1) ? CH - 2 : CH - 1;   // first consumed tp = T-2
        const int rlo = (c == 0) ? 1 : 0;
#pragma unroll 4
        for (int r = rhi; r >= rlo; r--) {
            const int tp = c * CH + r;                       // tp = t-1
            const float target = __shfl_sync(FULL, mcur, tag);
            const float tv = trColS[tag * K + lane];
            const float mprev = mc[r * K + lane];
            const float pprev = pcS[r * K + lane];
            const float v = (mprev + pprev) + tv;
            const unsigned msk = __ballot_sync(FULL, v == target);
            tag = __ffs(msk) - 1;
            ob[(size_t)tp * K] = (lane == tag) ? 1.0f : 0.0f;  // one-hot row tp
            mcur = mprev;
        }
        if (c - 2 >= 0) {
            const uint32_t md = ((c & 1) == 0) ? mA0 : mA1;  // (c-2) same parity
            const uint32_t pd = ((c & 1) == 0) ? potA0 : potA1;
            const char* gm = mB + (size_t)(c - 2) * 4096;
            const char* gp = pB + (size_t)(c - 2) * 4096;
#pragma unroll
            for (int i = 0; i < 8; i++) cp16(md + lane * 16 + i * 512, gm + lane * 16 + i * 512);
#pragma unroll
            for (int i = 0; i < 8; i++) cp16(pd + lane * 16 + i * 512, gp + lane * 16 + i * 512);
            CP_COMMIT();
            CP_WAIT(1);
            BARW();
        } else if (c - 1 >= 0) {
            CP_WAIT(0);
            BARW();
        }
    }
    // last step: t=1 -> tag(0), s(0) = pot(0)
    {
        const float target = __shfl_sync(FULL, mcur, tag);
        const float tv = trColS[tag * K + lane];
        const float v = pot0 + tv;
        tag = __ffs(__ballot_sync(FULL, v == target)) - 1;
        ob[0] = (lane == tag) ? 1.0f : 0.0f;                 // one-hot row 0
    }
}

extern "C" void kernel_launch(void* const* d_in, const int* in_sizes, int n_in,
                              void* d_out, int out_size)
{
    const float* pot   = (const float*)d_in[0];
    const float* trans = (const float*)d_in[1];
    float* outp        = (float*)d_out;
    crf_viterbi_kernel<<<B, K>>>(pot, trans, outp);
}

// round 7
// speedup vs baseline: 3.9311x; 1.0401x over previous
#include <cuda_runtime.h>
#include <cstdint>

#define B 512
#define T 2048
#define K 32
#define CH 32            // time steps per staged chunk
#define NCH (T / CH)     // 64 chunks
#define FULL 0xffffffffu

// m-trace: m[b][t][j] = max_i (s_i(t-1) + trans[i][j])  (slots t=1..T-1 used; last 2 chunks never hit gmem)
__device__ float g_m[(size_t)B * T * K];

#define ADD2(out, a, b) asm("add.rn.f32x2 %0, %1, %2;" : "=l"(out) : "l"(a), "l"(b))
#define UNPK(lo, hi, v) asm("mov.b64 {%0, %1}, %2;" : "=f"(lo), "=f"(hi) : "l"(v))
#define BARW()          asm volatile("bar.sync 0;" ::: "memory")

__device__ __forceinline__ void cp16(uint32_t saddr, const void* gptr) {
    asm volatile("cp.async.cg.shared.global [%0], [%1], 16;" :: "r"(saddr), "l"(gptr));
}
#define CP_COMMIT()  asm volatile("cp.async.commit_group;")
#define CP_WAIT(n)   asm volatile("cp.async.wait_group %0;" :: "n"(n))

// async-proxy bulk store smem -> gmem (1D, no tensormap)
__device__ __forceinline__ void bulk_s2g(void* gdst, uint32_t ssrc, uint32_t bytes) {
    asm volatile("cp.async.bulk.global.shared::cta.bulk_group [%0], [%1], %2;"
                 :: "l"(gdst), "r"(ssrc), "r"(bytes) : "memory");
}
#define BULK_COMMIT()    asm volatile("cp.async.bulk.commit_group;")
#define BULK_WAIT_RD(n)  asm volatile("cp.async.bulk.wait_group.read %0;" :: "n"(n))
#define BULK_WAIT(n)     asm volatile("cp.async.bulk.wait_group %0;" :: "n"(n))
#define FENCE_ASYNC()    asm volatile("fence.proxy.async.shared::cta;" ::: "memory")

__global__ void __launch_bounds__(32, 4) crf_viterbi_kernel(
    const float* __restrict__ pot,     // [B, T, K]
    const float* __restrict__ trans,   // [K, K]
    float* __restrict__ out)           // [B, T, K] one-hot
{
    __shared__ __align__(16) float potS[2][CH * K];   // 8 KB
    __shared__ __align__(16) float mS[2][CH * K];     // 8 KB
    __shared__ float trColS[K * K];                   // 4 KB : trColS[j*K+i] = trans[i][j]
    __shared__ __align__(16) float stS[2][K];

    const int lane = threadIdx.x;
    const int b    = blockIdx.x;
    const char* pB = (const char*)(pot + (size_t)b * T * K);
    const char* mB = (const char*)(g_m + (size_t)b * T * K);
    float* ob      = out + (size_t)b * T * K + lane;

    const uint32_t potA0 = (uint32_t)__cvta_generic_to_shared(potS[0]);
    const uint32_t potA1 = (uint32_t)__cvta_generic_to_shared(potS[1]);
    const uint32_t mA0   = (uint32_t)__cvta_generic_to_shared(mS[0]);
    const uint32_t mA1   = (uint32_t)__cvta_generic_to_shared(mS[1]);

    // packed transition column `lane`: tj2[q] = (trans[2q][lane], trans[2q+1][lane])
    unsigned long long tj2[16];
#pragma unroll
    for (int q = 0; q < 16; q++) {
        float lo = __ldg(trans + (2 * q) * K + lane);
        float hi = __ldg(trans + (2 * q + 1) * K + lane);
        asm("mov.b64 %0, {%1, %2};" : "=l"(tj2[q]) : "f"(lo), "f"(hi));
    }
    // transposed transitions for backtrack
#pragma unroll
    for (int i = 0; i < K; i++) trColS[lane * K + i] = trans[i * K + lane];

    // ---- stage forward chunks 0 and 1 ----
#pragma unroll
    for (int i = 0; i < 8; i++)
        cp16(potA0 + lane * 16 + i * 512, pB + lane * 16 + i * 512);
    CP_COMMIT();
#pragma unroll
    for (int i = 0; i < 8; i++)
        cp16(potA1 + lane * 16 + i * 512, pB + 4096 + lane * 16 + i * 512);
    CP_COMMIT();
    CP_WAIT(1);
    BARW();

    float s = potS[0][lane];           // s(0) = pot(0)
    const float pot0 = s;
    float mlast = 0.0f;

// one forward DP step (values only); writes m into the chunk's mS row
#define FSTEP(t, r, pc, mrow) do {                                        \
        const float pcur = (pc)[(r) * K + lane];                          \
        const int bb = (t) & 1;                                           \
        stS[bb][lane] = s;                                                \
        BARW();                                                           \
        const ulonglong2* sp = (const ulonglong2*)(stS[bb]);              \
        unsigned long long v2[16];                                        \
        _Pragma("unroll")                                                 \
        for (int q = 0; q < 8; q++) {                                     \
            ulonglong2 rr = sp[q];                                        \
            ADD2(v2[2 * q],     rr.x, tj2[2 * q]);                        \
            ADD2(v2[2 * q + 1], rr.y, tj2[2 * q + 1]);                    \
        }                                                                 \
        float m0[16];                                                     \
        _Pragma("unroll")                                                 \
        for (int q = 0; q < 16; q++) {                                    \
            float lo, hi; UNPK(lo, hi, v2[q]);                            \
            m0[q] = fmaxf(lo, hi);                                        \
        }                                                                 \
        float m1[8];                                                      \
        _Pragma("unroll")                                                 \
        for (int q = 0; q < 8; q++) m1[q] = fmaxf(m0[2*q], m0[2*q+1]);    \
        float m2[4];                                                      \
        _Pragma("unroll")                                                 \
        for (int q = 0; q < 4; q++) m2[q] = fmaxf(m1[2*q], m1[2*q+1]);    \
        const float m = fmaxf(fmaxf(m2[0], m2[1]), fmaxf(m2[2], m2[3]));  \
        (mrow)[(r) * K + lane] = m;                                       \
        s = m + pcur;                                                     \
        mlast = m;                                                        \
    } while (0)

    // ================= forward (values only) =================
    // chunk 0 (rows 1..31), peeled to avoid a per-step predicate
    {
        const float* pc = potS[0];
        float* mrow = mS[0];
#pragma unroll 8
        for (int r = 1; r < CH; r++) FSTEP(r, r, pc, mrow);
        // flush m chunk 0 to gmem (async proxy), stage pot chunk 2
        BARW();
        FENCE_ASYNC();
        if (lane == 0) {
            bulk_s2g((void*)(mB), mA0, 4096);
            BULK_COMMIT();
            BULK_WAIT_RD(1);
        }
        const char* src = pB + 2 * 4096;
#pragma unroll
        for (int i = 0; i < 8; i++)
            cp16(potA0 + lane * 16 + i * 512, src + lane * 16 + i * 512);
        CP_COMMIT();
        CP_WAIT(1);
        BARW();
    }
    for (int c = 1; c < NCH; c++) {
        const float* pc = potS[c & 1];
        float* mrow = mS[c & 1];
        for (int rb = 0; rb < CH / 8; rb++) {
#pragma unroll
            for (int k = 0; k < 8; k++) {
                const int r = rb * 8 + k;
                FSTEP(c * CH + r, r, pc, mrow);
            }
        }
        // flush m chunk c (skip last two: they stay resident for backtrack)
        BARW();
        if (c <= NCH - 3) {
            FENCE_ASYNC();
            if (lane == 0) {
                bulk_s2g((void*)(mB + (size_t)c * 4096), (c & 1) ? mA1 : mA0, 4096);
                BULK_COMMIT();
                BULK_WAIT_RD(1);
            }
        }
        if (c + 2 < NCH) {
            const uint32_t dst = ((c & 1) == 0) ? potA0 : potA1;
            const char* src = pB + (size_t)(c + 2) * 4096;
#pragma unroll
            for (int i = 0; i < 8; i++)
                cp16(dst + lane * 16 + i * 512, src + lane * 16 + i * 512);
            CP_COMMIT();
            CP_WAIT(1);
            BARW();
        } else if (c + 1 < NCH) {
            CP_WAIT(0);
            BARW();
        }
    }

    // ---- final tag: first-index argmax over lanes of s(T-1) ----
    float mm = s;
#pragma unroll
    for (int off = 16; off; off >>= 1) mm = fmaxf(mm, __shfl_xor_sync(FULL, mm, off));
    int tag = __ffs(__ballot_sync(FULL, s == mm)) - 1;
    ob[(size_t)(T - 1) * K] = (lane == tag) ? 1.0f : 0.0f;

    // make all bulk m-stores globally visible before re-reading via cp.async
    BULK_WAIT(0);
    BARW();

    // ================= backtrack: recompute argmax via ballot, fused one-hot ==========
    // chunks 63 and 62 (m and pot) are still resident in smem — no warm-up staging.
    float mcur = mlast;                            // m(T-1) across lanes

// one backtrack step at time tp (computes tag(tp) from tag(tp+1)); mc/pcS = chunk buffers
#define BSTEP(tp, r, mc, pcS) do {                                        \
        const float target = __shfl_sync(FULL, mcur, tag);                \
        const float tv = trColS[tag * K + lane];                          \
        const float mprev = (mc)[(r) * K + lane];                         \
        const float pprev = (pcS)[(r) * K + lane];                        \
        const float v = (mprev + pprev) + tv;                             \
        const unsigned msk = __ballot_sync(FULL, v == target);            \
        tag = __ffs(msk) - 1;                                             \
        ob[(size_t)(tp) * K] = (lane == tag) ? 1.0f : 0.0f;               \
        mcur = mprev;                                                     \
    } while (0)

// stage m+pot of chunk (c-2) into buffer ((c)&1), then ensure chunk (c-1) ready
#define STAGE_BT(c) do {                                                  \
        const uint32_t md = (((c) & 1) == 0) ? mA0 : mA1;                 \
        const uint32_t pd = (((c) & 1) == 0) ? potA0 : potA1;             \
        const char* gm = mB + (size_t)((c) - 2) * 4096;                   \
        const char* gp = pB + (size_t)((c) - 2) * 4096;                   \
        _Pragma("unroll")                                                 \
        for (int i = 0; i < 8; i++) cp16(md + lane*16 + i*512, gm + lane*16 + i*512); \
        _Pragma("unroll")                                                 \
        for (int i = 0; i < 8; i++) cp16(pd + lane*16 + i*512, gp + lane*16 + i*512); \
        CP_COMMIT();                                                      \
        CP_WAIT(1);                                                       \
        BARW();                                                           \
    } while (0)

    // chunk 63: rows 30..0 (tp = 2046..2016)
    {
        const float* mc  = mS[1];
        const float* pcS = potS[1];
#pragma unroll 8
        for (int r = CH - 2; r >= 0; r--) BSTEP(63 * CH + r, r, mc, pcS);
        STAGE_BT(63);
    }
    // chunks 62..1: full 32 rows each
    for (int c = NCH - 2; c >= 1; c--) {
        const float* mc  = mS[c & 1];
        const float* pcS = potS[c & 1];
#pragma unroll 8
        for (int r = CH - 1; r >= 0; r--) BSTEP(c * CH + r, r, mc, pcS);
        if (c >= 2) {
            STAGE_BT(c);
        } else {
            CP_WAIT(0);
            BARW();
        }
    }
    // chunk 0: rows 31..1 (tp = 31..1)
    {
        const float* mc  = mS[0];
        const float* pcS = potS[0];
#pragma unroll 8
        for (int r = CH - 1; r >= 1; r--) BSTEP(r, r, mc, pcS);
    }
    // last step: t=1 -> tag(0), s(0) = pot(0)
    {
        const float target = __shfl_sync(FULL, mcur, tag);
        const float tv = trColS[tag * K + lane];
        const float v = pot0 + tv;
        tag = __ffs(__ballot_sync(FULL, v == target)) - 1;
        ob[0] = (lane == tag) ? 1.0f : 0.0f;
    }
}

extern "C" void kernel_launch(void* const* d_in, const int* in_sizes, int n_in,
                              void* d_out, int out_size)
{
    const float* pot   = (const float*)d_in[0];
    const float* trans = (const float*)d_in[1];
    float* outp        = (float*)d_out;
    crf_viterbi_kernel<<<B, K>>>(pot, trans, outp);
}

// round 8
// speedup vs baseline: 4.2176x; 1.0729x over previous
#include <cuda_runtime.h>
#include <cstdint>

#define B 512
#define T 2048
#define K 32
#define CH 16            // time steps per staged chunk
#define NCH (T / CH)     // 128 chunks
#define WPC 4            // warps (batches) per CTA
#define CHB (CH * K * 4) // chunk bytes = 2048
#define FULL 0xffffffffu

// m-trace (chunked layout == smem layout): last 2 chunks never hit gmem
__device__ float g_m[(size_t)B * T * K];

#define ADD2(out, a, b) asm("add.rn.f32x2 %0, %1, %2;" : "=l"(out) : "l"(a), "l"(b))
#define UNPK(lo, hi, v) asm("mov.b64 {%0, %1}, %2;" : "=f"(lo), "=f"(hi) : "l"(v))
#define WSYNC()         __syncwarp()

__device__ __forceinline__ void cp16(uint32_t saddr, const void* gptr) {
    asm volatile("cp.async.cg.shared.global [%0], [%1], 16;" :: "r"(saddr), "l"(gptr));
}
#define CP_COMMIT()  asm volatile("cp.async.commit_group;")
#define CP_WAIT(n)   asm volatile("cp.async.wait_group %0;" :: "n"(n))

__device__ __forceinline__ void bulk_s2g(void* gdst, uint32_t ssrc, uint32_t bytes) {
    asm volatile("cp.async.bulk.global.shared::cta.bulk_group [%0], [%1], %2;"
                 :: "l"(gdst), "r"(ssrc), "r"(bytes) : "memory");
}
#define BULK_COMMIT()    asm volatile("cp.async.bulk.commit_group;")
#define BULK_WAIT_RD(n)  asm volatile("cp.async.bulk.wait_group.read %0;" :: "n"(n))
#define BULK_WAIT(n)     asm volatile("cp.async.bulk.wait_group %0;" :: "n"(n))
#define FENCE_ASYNC()    asm volatile("fence.proxy.async.shared::cta;" ::: "memory")

__global__ void __launch_bounds__(WPC * 32, 1) crf_viterbi_kernel(
    const float* __restrict__ pot,     // [B, T, K]
    const float* __restrict__ trans,   // [K, K]
    float* __restrict__ out)           // [B, T, K] one-hot
{
    __shared__ __align__(16) float potS[WPC][2][CH * K];   // 16 KB
    __shared__ __align__(16) float mS[WPC][2][CH * K];     // 16 KB
    __shared__ float trColS[K * K];                        // 4 KB : trColS[j*K+i] = trans[i][j]
    __shared__ __align__(16) float stS[WPC][2][K];         // 1 KB

    const int lane = threadIdx.x & 31;
    const int w    = threadIdx.x >> 5;
    const int b    = blockIdx.x * WPC + w;

    const char* pB = (const char*)(pot + (size_t)b * T * K);
    const char* mB = (const char*)(g_m + (size_t)b * T * K);
    float* ob      = out + (size_t)b * T * K + lane;

    float* potW0 = potS[w][0];  float* potW1 = potS[w][1];
    float* mW0   = mS[w][0];    float* mW1   = mS[w][1];
    const uint32_t potA0 = (uint32_t)__cvta_generic_to_shared(potW0);
    const uint32_t potA1 = (uint32_t)__cvta_generic_to_shared(potW1);
    const uint32_t mA0   = (uint32_t)__cvta_generic_to_shared(mW0);
    const uint32_t mA1   = (uint32_t)__cvta_generic_to_shared(mW1);

    // packed transition column `lane`: tj2[q] = (trans[2q][lane], trans[2q+1][lane])
    unsigned long long tj2[16];
#pragma unroll
    for (int q = 0; q < 16; q++) {
        float lo = __ldg(trans + (2 * q) * K + lane);
        float hi = __ldg(trans + (2 * q + 1) * K + lane);
        asm("mov.b64 %0, {%1, %2};" : "=l"(tj2[q]) : "f"(lo), "f"(hi));
    }
    // transposed transitions for backtrack (shared across warps, written by warp 0)
    if (w == 0) {
#pragma unroll
        for (int i = 0; i < K; i++) trColS[lane * K + i] = trans[i * K + lane];
    }
    __syncthreads();

    // ---- stage forward chunks 0 and 1 (4 x cp16 per lane per chunk) ----
#pragma unroll
    for (int i = 0; i < 4; i++)
        cp16(potA0 + lane * 16 + i * 512, pB + lane * 16 + i * 512);
    CP_COMMIT();
#pragma unroll
    for (int i = 0; i < 4; i++)
        cp16(potA1 + lane * 16 + i * 512, pB + CHB + lane * 16 + i * 512);
    CP_COMMIT();
    CP_WAIT(1);
    WSYNC();

    float s = potW0[lane];            // s(0) = pot(0)
    const float pot0 = s;
    float mlast = 0.0f;

// one forward DP step (values only); no per-step sync: same-warp STS->LDS is in order
#define FSTEP(t, r, pc, mrow) do {                                        \
        const float pcur = (pc)[(r) * K + lane];                          \
        float* sb = stS[w][(t) & 1];                                      \
        sb[lane] = s;                                                     \
        const ulonglong2* sp = (const ulonglong2*)sb;                     \
        unsigned long long v2[16];                                        \
        _Pragma("unroll")                                                 \
        for (int q = 0; q < 8; q++) {                                     \
            ulonglong2 rr = sp[q];                                        \
            ADD2(v2[2 * q],     rr.x, tj2[2 * q]);                        \
            ADD2(v2[2 * q + 1], rr.y, tj2[2 * q + 1]);                    \
        }                                                                 \
        float m0[16];                                                     \
        _Pragma("unroll")                                                 \
        for (int q = 0; q < 16; q++) {                                    \
            float lo, hi; UNPK(lo, hi, v2[q]);                            \
            m0[q] = fmaxf(lo, hi);                                        \
        }                                                                 \
        float m1[8];                                                      \
        _Pragma("unroll")                                                 \
        for (int q = 0; q < 8; q++) m1[q] = fmaxf(m0[2*q], m0[2*q+1]);    \
        float m2[4];                                                      \
        _Pragma("unroll")                                                 \
        for (int q = 0; q < 4; q++) m2[q] = fmaxf(m1[2*q], m1[2*q+1]);    \
        const float m = fmaxf(fmaxf(m2[0], m2[1]), fmaxf(m2[2], m2[3]));  \
        (mrow)[(r) * K + lane] = m;                                       \
        s = m + pcur;                                                     \
        mlast = m;                                                        \
    } while (0)

    // ================= forward =================
    // chunk 0 (rows 1..15), peeled
    {
#pragma unroll 8
        for (int r = 1; r < CH; r++) FSTEP(r, r, potW0, mW0);
        WSYNC();
        FENCE_ASYNC();
        if (lane == 0) {
            bulk_s2g((void*)mB, mA0, CHB);
            BULK_COMMIT();
            BULK_WAIT_RD(1);
        }
        const char* src = pB + 2 * CHB;
#pragma unroll
        for (int i = 0; i < 4; i++)
            cp16(potA0 + lane * 16 + i * 512, src + lane * 16 + i * 512);
        CP_COMMIT();
        CP_WAIT(1);
        WSYNC();
    }
    for (int c = 1; c < NCH; c++) {
        const float* pc = (c & 1) ? potW1 : potW0;
        float* mrow     = (c & 1) ? mW1 : mW0;
#pragma unroll
        for (int r = 0; r < CH; r++) FSTEP(c * CH + r, r, pc, mrow);
        WSYNC();
        if (c <= NCH - 3) {
            FENCE_ASYNC();
            if (lane == 0) {
                bulk_s2g((void*)(mB + (size_t)c * CHB), (c & 1) ? mA1 : mA0, CHB);
                BULK_COMMIT();
                BULK_WAIT_RD(1);
            }
        }
        if (c + 2 < NCH) {
            const uint32_t dst = ((c & 1) == 0) ? potA0 : potA1;
            const char* src = pB + (size_t)(c + 2) * CHB;
#pragma unroll
            for (int i = 0; i < 4; i++)
                cp16(dst + lane * 16 + i * 512, src + lane * 16 + i * 512);
            CP_COMMIT();
            CP_WAIT(1);
            WSYNC();
        } else if (c + 1 < NCH) {
            CP_WAIT(0);
            WSYNC();
        }
    }

    // ---- final tag: first-index argmax over lanes of s(T-1) ----
    float mm = s;
#pragma unroll
    for (int off = 16; off; off >>= 1) mm = fmaxf(mm, __shfl_xor_sync(FULL, mm, off));
    int tag = __ffs(__ballot_sync(FULL, s == mm)) - 1;
    ob[(size_t)(T - 1) * K] = (lane == tag) ? 1.0f : 0.0f;

    // all bulk m-stores globally visible before re-reading via cp.async
    if (lane == 0) BULK_WAIT(0);
    WSYNC();

    // ================= backtrack (chunks NCH-1, NCH-2 still resident) ===============
    float mcur = mlast;

#define BSTEP(tp, r, mc, pcS) do {                                        \
        const float target = __shfl_sync(FULL, mcur, tag);                \
        const float tv = trColS[tag * K + lane];                          \
        const float mprev = (mc)[(r) * K + lane];                         \
        const float pprev = (pcS)[(r) * K + lane];                        \
        const float v = (mprev + pprev) + tv;                             \
        const unsigned msk = __ballot_sync(FULL, v == target);            \
        tag = __ffs(msk) - 1;                                             \
        ob[(size_t)(tp) * K] = (lane == tag) ? 1.0f : 0.0f;               \
        mcur = mprev;                                                     \
    } while (0)

#define STAGE_BT(c) do {                                                  \
        const uint32_t md = (((c) & 1) == 0) ? mA0 : mA1;                 \
        const uint32_t pd = (((c) & 1) == 0) ? potA0 : potA1;             \
        const char* gm = mB + (size_t)((c) - 2) * CHB;                    \
        const char* gp = pB + (size_t)((c) - 2) * CHB;                    \
        _Pragma("unroll")                                                 \
        for (int i = 0; i < 4; i++) cp16(md + lane*16 + i*512, gm + lane*16 + i*512); \
        _Pragma("unroll")                                                 \
        for (int i = 0; i < 4; i++) cp16(pd + lane*16 + i*512, gp + lane*16 + i*512); \
        CP_COMMIT();                                                      \
        CP_WAIT(1);                                                       \
        WSYNC();                                                          \
    } while (0)

    // chunk NCH-1: rows CH-2..0
    {
        const float* mc  = mW1;   // (NCH-1)&1 == 1
        const float* pcS = potW1;
#pragma unroll
        for (int r = CH - 2; r >= 0; r--) BSTEP((NCH - 1) * CH + r, r, mc, pcS);
        STAGE_BT(NCH - 1);
    }
    // chunks NCH-2..1
    for (int c = NCH - 2; c >= 1; c--) {
        const float* mc  = (c & 1) ? mW1 : mW0;
        const float* pcS = (c & 1) ? potW1 : potW0;
#pragma unroll
        for (int r = CH - 1; r >= 0; r--) BSTEP(c * CH + r, r, mc, pcS);
        if (c >= 2) {
            STAGE_BT(c);
        } else {
            CP_WAIT(0);
            WSYNC();
        }
    }
    // chunk 0: rows CH-1..1
    {
#pragma unroll
        for (int r = CH - 1; r >= 1; r--) BSTEP(r, r, mW0, potW0);
    }
    // last step: t=1 -> tag(0)
    {
        const float target = __shfl_sync(FULL, mcur, tag);
        const float tv = trColS[tag * K + lane];
        const float v = pot0 + tv;
        tag = __ffs(__ballot_sync(FULL, v == target)) - 1;
        ob[0] = (lane == tag) ? 1.0f : 0.0f;
    }
}

extern "C" void kernel_launch(void* const* d_in, const int* in_sizes, int n_in,
                              void* d_out, int out_size)
{
    const float* pot   = (const float*)d_in[0];
    const float* trans = (const float*)d_in[1];
    float* outp        = (float*)d_out;
    crf_viterbi_kernel<<<B / WPC, WPC * 32>>>(pot, trans, outp);
}

// round 9
// speedup vs baseline: 4.2457x; 1.0066x over previous
#include <cuda_runtime.h>
#include <cstdint>

#define B 512
#define T 2048
#define K 32
#define CH 64            // time steps per staged chunk
#define NCH (T / CH)     // 32 chunks
#define WPC 4            // warps (batches) per CTA
#define CHB (CH * K * 4) // chunk bytes = 8192
#define FULL 0xffffffffu

// dynamic smem layout (floats): pot[WPC][2][CH*K] | m[WPC][2][CH*K] | trCol[K*K] | st[WPC][K]
#define POT_F (WPC * 2 * CH * K)
#define M_F   (WPC * 2 * CH * K)
#define SMEM_DYN_BYTES ((POT_F + M_F + K * K + WPC * K) * 4)

// m-trace (chunked layout == smem layout): last 2 chunks never hit gmem
__device__ float g_m[(size_t)B * T * K];

#define ADD2(out, a, b) asm("add.rn.f32x2 %0, %1, %2;" : "=l"(out) : "l"(a), "l"(b))
#define UNPK(lo, hi, v) asm("mov.b64 {%0, %1}, %2;" : "=f"(lo), "=f"(hi) : "l"(v))
#define WSYNC()         __syncwarp()

__device__ __forceinline__ void cp16(uint32_t saddr, const void* gptr) {
    asm volatile("cp.async.cg.shared.global [%0], [%1], 16;" :: "r"(saddr), "l"(gptr));
}
#define CP_COMMIT()  asm volatile("cp.async.commit_group;")
#define CP_WAIT(n)   asm volatile("cp.async.wait_group %0;" :: "n"(n))

__device__ __forceinline__ void bulk_s2g(void* gdst, uint32_t ssrc, uint32_t bytes) {
    asm volatile("cp.async.bulk.global.shared::cta.bulk_group [%0], [%1], %2;"
                 :: "l"(gdst), "r"(ssrc), "r"(bytes) : "memory");
}
#define BULK_COMMIT()    asm volatile("cp.async.bulk.commit_group;")
#define BULK_WAIT_RD(n)  asm volatile("cp.async.bulk.wait_group.read %0;" :: "n"(n))
#define BULK_WAIT(n)     asm volatile("cp.async.bulk.wait_group %0;" :: "n"(n))
#define FENCE_ASYNC()    asm volatile("fence.proxy.async.shared::cta;" ::: "memory")

__global__ void __launch_bounds__(WPC * 32, 1) crf_viterbi_kernel(
    const float* __restrict__ pot,     // [B, T, K]
    const float* __restrict__ trans,   // [K, K]
    float* __restrict__ out)           // [B, T, K] one-hot
{
    extern __shared__ __align__(16) float dyn[];
    float* potBase = dyn;
    float* mBase   = dyn + POT_F;
    float* trColS  = mBase + M_F;              // trColS[j*K+i] = trans[i][j]

    const int lane = threadIdx.x & 31;
    const int w    = threadIdx.x >> 5;
    const int b    = blockIdx.x * WPC + w;

    const char* pB = (const char*)(pot + (size_t)b * T * K);
    const char* mB = (const char*)(g_m + (size_t)b * T * K);
    float* ob      = out + (size_t)b * T * K + lane;

    float* potW0 = potBase + (w * 2 + 0) * CH * K;
    float* potW1 = potBase + (w * 2 + 1) * CH * K;
    float* mW0   = mBase + (w * 2 + 0) * CH * K;
    float* mW1   = mBase + (w * 2 + 1) * CH * K;
    float* stW   = trColS + K * K + w * K;
    const uint32_t potA0 = (uint32_t)__cvta_generic_to_shared(potW0);
    const uint32_t potA1 = (uint32_t)__cvta_generic_to_shared(potW1);
    const uint32_t mA0   = (uint32_t)__cvta_generic_to_shared(mW0);
    const uint32_t mA1   = (uint32_t)__cvta_generic_to_shared(mW1);

    // packed transition column `lane`: tj2[q] = (trans[2q][lane], trans[2q+1][lane])
    unsigned long long tj2[16];
#pragma unroll
    for (int q = 0; q < 16; q++) {
        float lo = __ldg(trans + (2 * q) * K + lane);
        float hi = __ldg(trans + (2 * q + 1) * K + lane);
        asm("mov.b64 %0, {%1, %2};" : "=l"(tj2[q]) : "f"(lo), "f"(hi));
    }
    // transposed transitions for backtrack (shared across warps, written by warp 0)
    if (w == 0) {
#pragma unroll
        for (int i = 0; i < K; i++) trColS[lane * K + i] = trans[i * K + lane];
    }
    __syncthreads();

    // ---- stage forward chunks 0 and 1 (16 x cp16 per lane per chunk) ----
#pragma unroll
    for (int i = 0; i < 16; i++)
        cp16(potA0 + lane * 16 + i * 512, pB + lane * 16 + i * 512);
    CP_COMMIT();
#pragma unroll
    for (int i = 0; i < 16; i++)
        cp16(potA1 + lane * 16 + i * 512, pB + CHB + lane * 16 + i * 512);
    CP_COMMIT();
    CP_WAIT(1);
    WSYNC();

    float s = potW0[lane];            // s(0) = pot(0)
    const float pot0 = s;
    float mlast = 0.0f;

// one forward DP step (values only); no per-step sync: same-warp STS->LDS is in order
#define FSTEP(r, pc, mrow) do {                                           \
        const float pcur = (pc)[(r) * K + lane];                          \
        stW[lane] = s;                                                    \
        const ulonglong2* sp = (const ulonglong2*)stW;                    \
        unsigned long long v2[16];                                        \
        _Pragma("unroll")                                                 \
        for (int q = 0; q < 8; q++) {                                     \
            ulonglong2 rr = sp[q];                                        \
            ADD2(v2[2 * q],     rr.x, tj2[2 * q]);                        \
            ADD2(v2[2 * q + 1], rr.y, tj2[2 * q + 1]);                    \
        }                                                                 \
        float m0[16];                                                     \
        _Pragma("unroll")                                                 \
        for (int q = 0; q < 16; q++) {                                    \
            float lo, hi; UNPK(lo, hi, v2[q]);                            \
            m0[q] = fmaxf(lo, hi);                                        \
        }                                                                 \
        float m1[8];                                                      \
        _Pragma("unroll")                                                 \
        for (int q = 0; q < 8; q++) m1[q] = fmaxf(m0[2*q], m0[2*q+1]);    \
        float m2[4];                                                      \
        _Pragma("unroll")                                                 \
        for (int q = 0; q < 4; q++) m2[q] = fmaxf(m1[2*q], m1[2*q+1]);    \
        const float m = fmaxf(fmaxf(m2[0], m2[1]), fmaxf(m2[2], m2[3]));  \
        (mrow)[(r) * K + lane] = m;                                       \
        s = m + pcur;                                                     \
        mlast = m;                                                        \
    } while (0)

    // ================= forward =================
    // chunk 0 (rows 1..CH-1), peeled
    {
#pragma unroll 8
        for (int r = 1; r < CH; r++) FSTEP(r, potW0, mW0);
        WSYNC();
        FENCE_ASYNC();
        if (lane == 0) {
            bulk_s2g((void*)mB, mA0, CHB);
            BULK_COMMIT();
            BULK_WAIT_RD(1);
        }
        const char* src = pB + 2 * (size_t)CHB;
#pragma unroll
        for (int i = 0; i < 16; i++)
            cp16(potA0 + lane * 16 + i * 512, src + lane * 16 + i * 512);
        CP_COMMIT();
        CP_WAIT(1);
        WSYNC();
    }
    for (int c = 1; c < NCH; c++) {
        const float* pc = (c & 1) ? potW1 : potW0;
        float* mrow     = (c & 1) ? mW1 : mW0;
#pragma unroll 8
        for (int r = 0; r < CH; r++) FSTEP(r, pc, mrow);
        WSYNC();
        if (c <= NCH - 3) {
            FENCE_ASYNC();
            if (lane == 0) {
                bulk_s2g((void*)(mB + (size_t)c * CHB), (c & 1) ? mA1 : mA0, CHB);
                BULK_COMMIT();
                BULK_WAIT_RD(1);
            }
        }
        if (c + 2 < NCH) {
            const uint32_t dst = ((c & 1) == 0) ? potA0 : potA1;
            const char* src = pB + (size_t)(c + 2) * CHB;
#pragma unroll
            for (int i = 0; i < 16; i++)
                cp16(dst + lane * 16 + i * 512, src + lane * 16 + i * 512);
            CP_COMMIT();
            CP_WAIT(1);
            WSYNC();
        } else if (c + 1 < NCH) {
            CP_WAIT(0);
            WSYNC();
        }
    }

    // ---- final tag: first-index argmax over lanes of s(T-1) ----
    float mm = s;
#pragma unroll
    for (int off = 16; off; off >>= 1) mm = fmaxf(mm, __shfl_xor_sync(FULL, mm, off));
    int tag = __ffs(__ballot_sync(FULL, s == mm)) - 1;
    ob[(size_t)(T - 1) * K] = (lane == tag) ? 1.0f : 0.0f;

    // all bulk m-stores globally visible before re-reading via cp.async
    if (lane == 0) BULK_WAIT(0);
    WSYNC();

    // ================= backtrack (chunks NCH-1, NCH-2 still resident) ===============
    float mcur = mlast;

#define BSTEP(tp, r, mc, pcS) do {                                        \
        const float target = __shfl_sync(FULL, mcur, tag);                \
        const float tv = trColS[tag * K + lane];                          \
        const float mprev = (mc)[(r) * K + lane];                         \
        const float pprev = (pcS)[(r) * K + lane];                        \
        const float v = (mprev + pprev) + tv;                             \
        const unsigned msk = __ballot_sync(FULL, v == target);            \
        tag = __ffs(msk) - 1;                                             \
        ob[(size_t)(tp) * K] = (lane == tag) ? 1.0f : 0.0f;               \
        mcur = mprev;                                                     \
    } while (0)

#define STAGE_BT(c) do {                                                  \
        const uint32_t md = (((c) & 1) == 0) ? mA0 : mA1;                 \
        const uint32_t pd = (((c) & 1) == 0) ? potA0 : potA1;             \
        const char* gm = mB + (size_t)((c) - 2) * CHB;                    \
        const char* gp = pB + (size_t)((c) - 2) * CHB;                    \
        _Pragma("unroll")                                                 \
        for (int i = 0; i < 16; i++) cp16(md + lane*16 + i*512, gm + lane*16 + i*512); \
        _Pragma("unroll")                                                 \
        for (int i = 0; i < 16; i++) cp16(pd + lane*16 + i*512, gp + lane*16 + i*512); \
        CP_COMMIT();                                                      \
        CP_WAIT(1);                                                       \
        WSYNC();                                                          \
    } while (0)

    // chunk NCH-1: rows CH-2..0
    {
        const float* mc  = mW1;   // (NCH-1)&1 == 1
        const float* pcS = potW1;
#pragma unroll 8
        for (int r = CH - 2; r >= 0; r--) BSTEP((NCH - 1) * CH + r, r, mc, pcS);
        STAGE_BT(NCH - 1);
    }
    // chunks NCH-2..1
    for (int c = NCH - 2; c >= 1; c--) {
        const float* mc  = (c & 1) ? mW1 : mW0;
        const float* pcS = (c & 1) ? potW1 : potW0;
#pragma unroll 8
        for (int r = CH - 1; r >= 0; r--) BSTEP(c * CH + r, r, mc, pcS);
        if (c >= 2) {
            STAGE_BT(c);
        } else {
            CP_WAIT(0);
            WSYNC();
        }
    }
    // chunk 0: rows CH-1..1
    {
#pragma unroll 8
        for (int r = CH - 1; r >= 1; r--) BSTEP(r, r, mW0, potW0);
    }
    // last step: t=1 -> tag(0)
    {
        const float target = __shfl_sync(FULL, mcur, tag);
        const float tv = trColS[tag * K + lane];
        const float v = pot0 + tv;
        tag = __ffs(__ballot_sync(FULL, v == target)) - 1;
        ob[0] = (lane == tag) ? 1.0f : 0.0f;
    }
}

extern "C" void kernel_launch(void* const* d_in, const int* in_sizes, int n_in,
                              void* d_out, int out_size)
{
    const float* pot   = (const float*)d_in[0];
    const float* trans = (const float*)d_in[1];
    float* outp        = (float*)d_out;
    cudaFuncSetAttribute(crf_viterbi_kernel,
                         cudaFuncAttributeMaxDynamicSharedMemorySize, SMEM_DYN_BYTES);
    crf_viterbi_kernel<<<B / WPC, WPC * 32, SMEM_DYN_BYTES>>>(pot, trans, outp);
}